// round 10
// baseline (speedup 1.0000x reference)
#include <cuda_runtime.h>
#include <cuda_bf16.h>
#include <cstdint>

// ---------------- problem constants ----------------
#define M_TOT 2048
#define K_DIM 256
#define N_LUT 5532
#define N_CQ  5000
#define N_TOT 10788
#define N_PAD 11008            // 43 * 256 (zero-padded B rows)
#define KB    512              // packed K per row: [hi(256) | lo(256)] bf16
#define SCALE 30.0f

// ---------------- GEMM tiling ----------------
#define BM 128
#define BN 256
#define NCHUNK 12              // 12 chunks of 64 bf16 = K_eff 768 (3 slabs x 4)
#define STAGES 3
#define STAGE_A 16384          // 128 rows x 128B
#define STAGE_B 32768          // 256 rows x 128B
#define STAGE_BYTES (STAGE_A + STAGE_B)
#define SMEM_BYTES (1024 + STAGES * STAGE_BYTES)   // 148480
#define NTHREADS 256

typedef unsigned int u32;
typedef unsigned long long u64;

// ---------------- device scratch (no allocs allowed) ----------------
__device__ __align__(1024) __nv_bfloat16 g_A[(size_t)M_TOT * KB];   // 2 MB
__device__ __align__(1024) __nv_bfloat16 g_B[(size_t)N_PAD * KB];   // ~11.3 MB

// ---------------- PTX helpers (plain sm_80+ features only) ----------------
static __device__ __forceinline__ u32 cvta_smem(const void* p) {
    u32 a;
    asm("{ .reg .u64 t; cvta.to.shared.u64 t, %1; cvt.u32.u64 %0, t; }" : "=r"(a) : "l"(p));
    return a;
}

static __device__ __forceinline__ void cp_async16(u32 dst, const void* src) {
    asm volatile("cp.async.cg.shared.global [%0], [%1], 16;" :: "r"(dst), "l"(src) : "memory");
}

static __device__ __forceinline__ void ldmatrix4(u32* f, u32 addr) {
    asm volatile("ldmatrix.sync.aligned.m8n8.x4.shared.b16 {%0,%1,%2,%3}, [%4];"
                 : "=r"(f[0]), "=r"(f[1]), "=r"(f[2]), "=r"(f[3]) : "r"(addr));
}

static __device__ __forceinline__ void mma_bf16(float* c, const u32* a, const u32* b) {
    asm volatile(
        "mma.sync.aligned.m16n8k16.row.col.f32.bf16.bf16.f32 "
        "{%0,%1,%2,%3}, {%4,%5,%6,%7}, {%8,%9}, {%0,%1,%2,%3};"
        : "+f"(c[0]), "+f"(c[1]), "+f"(c[2]), "+f"(c[3])
        : "r"(a[0]), "r"(a[1]), "r"(a[2]), "r"(a[3]), "r"(b[0]), "r"(b[1]));
}

// ---------------- pack kernel: fp32 -> [bf16 hi | bf16 lo] ----------------
__global__ void pack_kernel(const float* __restrict__ A, const float* __restrict__ lut,
                            const float* __restrict__ cq, const float* __restrict__ nonid)
{
    const int t = threadIdx.x;
    const int row = blockIdx.x * 4 + (t >> 6);     // 4 rows per block
    const int k0 = (t & 63) * 4;

    const float* src;
    __nv_bfloat16* dst;
    if (row < M_TOT) {
        src = A + (size_t)row * K_DIM;
        dst = g_A + (size_t)row * KB;
    } else {
        const int n = row - M_TOT;
        dst = g_B + (size_t)n * KB;
        if (n < N_LUT)              src = lut   + (size_t)n * K_DIM;
        else if (n < N_LUT + N_CQ)  src = cq    + (size_t)(n - N_LUT) * K_DIM;
        else if (n < N_TOT)         src = nonid + (size_t)(n - N_LUT - N_CQ) * K_DIM;
        else                        src = nullptr;   // zero padding rows
    }

    float4 v = src ? *reinterpret_cast<const float4*>(src + k0)
                   : make_float4(0.f, 0.f, 0.f, 0.f);

    float x[4] = {v.x, v.y, v.z, v.w};
    unsigned short h[4], l[4];
    #pragma unroll
    for (int i = 0; i < 4; i++) {
        __nv_bfloat16 hb = __float2bfloat16(x[i]);
        float r = x[i] - __bfloat162float(hb);
        __nv_bfloat16 lb = __float2bfloat16(r);
        h[i] = __bfloat16_as_ushort(hb);
        l[i] = __bfloat16_as_ushort(lb);
    }
    uint2 hp, lp;
    hp.x = ((u32)h[1] << 16) | h[0];
    hp.y = ((u32)h[3] << 16) | h[2];
    lp.x = ((u32)l[1] << 16) | l[0];
    lp.y = ((u32)l[3] << 16) | l[2];
    *reinterpret_cast<uint2*>(dst + k0)         = hp;
    *reinterpret_cast<uint2*>(dst + K_DIM + k0) = lp;
}

// ---------------- main GEMM: 128x256 CTA tile, 64x64 warp tile ----------------
__global__ void __launch_bounds__(NTHREADS, 1)
oim_mma_gemm(float* __restrict__ out)
{
    extern __shared__ char smem_raw[];
    u32 base = cvta_smem(smem_raw);
    base = (base + 1023u) & ~1023u;        // 1024-align tile region

    const int tid = threadIdx.x;
    const int lid = tid & 31;
    const int wid = tid >> 5;
    const int wm  = wid & 1;               // 2 warps in M -> 64 rows each
    const int wn  = wid >> 1;              // 4 warps in N -> 64 cols each

    const int m0 = blockIdx.y * BM;
    const int n0 = blockIdx.x * BN;

    // ---- producer mapping
    const int r0  = tid >> 3;              // 0..31
    const int seg = tid & 7;               // 16B segment within 128B row

    // ---- ldmatrix lane constants
    const int mat = lid >> 3, rr = lid & 7;
    const int a_row = wm * 64 + ((mat & 1) << 3) + rr;   // + mi*16
    const u32 a_xor = (u32)(a_row & 7);
    const int a_ck  = mat >> 1;                           // 16B chunk within k16
    const int b_row = wn * 64 + ((mat >> 1) << 3) + rr;   // + p*16
    const u32 b_xor = (u32)(b_row & 7);
    const int b_ck  = mat & 1;

    float acc[4][8][4];
    #pragma unroll
    for (int i = 0; i < 4; i++)
        #pragma unroll
        for (int j = 0; j < 8; j++)
            #pragma unroll
            for (int v = 0; v < 4; v++)
                acc[i][j][v] = 0.f;

    // chunk c -> slab offsets within packed 512-wide rows
    // chunks 0-3: A hi x B hi ; 4-7: A hi x B lo ; 8-11: A lo x B hi
    auto issue_chunk = [&](int c) {
        const int aoff = (c < 8) ? ((c & 3) << 6) : (256 + ((c - 8) << 6));
        const int boff = (c < 4) ? (c << 6)
                       : ((c < 8) ? (256 + ((c - 4) << 6)) : ((c - 8) << 6));
        const u32 stage = base + (u32)(c % STAGES) * STAGE_BYTES;
        const __nv_bfloat16* asrc = g_A + (size_t)(m0 + r0) * KB + aoff + seg * 8;
        const __nv_bfloat16* bsrc = g_B + (size_t)(n0 + r0) * KB + boff + seg * 8;
        #pragma unroll
        for (int j = 0; j < 4; ++j) {
            const u32 rel = (u32)((r0 + j * 32) * 128 + seg * 16);
            const u32 sw  = rel ^ ((rel >> 3) & 0x70u);
            cp_async16(stage + sw, asrc + (size_t)j * 32 * KB);
        }
        #pragma unroll
        for (int j = 0; j < 8; ++j) {
            const u32 rel = (u32)((r0 + j * 32) * 128 + seg * 16);
            const u32 sw  = rel ^ ((rel >> 3) & 0x70u);
            cp_async16(stage + STAGE_A + sw, bsrc + (size_t)j * 32 * KB);
        }
        asm volatile("cp.async.commit_group;" ::: "memory");
    };

    issue_chunk(0);
    issue_chunk(1);

    for (int q = 0; q < NCHUNK; ++q) {
        if (q < NCHUNK - 2) asm volatile("cp.async.wait_group 1;" ::: "memory");
        else                asm volatile("cp.async.wait_group 0;" ::: "memory");
        __syncthreads();   // chunk q resident everywhere; prior reads of its stage done

        if (q + 2 < NCHUNK) issue_chunk(q + 2);

        const u32 sA = base + (u32)(q % STAGES) * STAGE_BYTES;
        const u32 sB = sA + STAGE_A;

        #pragma unroll
        for (int ks = 0; ks < 4; ++ks) {
            u32 af[4][4];
            #pragma unroll
            for (int mi = 0; mi < 4; ++mi) {
                const u32 row  = (u32)(a_row + mi * 16);
                const u32 addr = sA + row * 128u + ((((u32)(ks * 2 + a_ck)) ^ a_xor) << 4);
                ldmatrix4(af[mi], addr);
            }
            u32 bf[8][2];
            #pragma unroll
            for (int p = 0; p < 4; ++p) {
                const u32 row  = (u32)(b_row + p * 16);
                const u32 addr = sB + row * 128u + ((((u32)(ks * 2 + b_ck)) ^ b_xor) << 4);
                u32 t[4];
                ldmatrix4(t, addr);
                bf[p * 2][0] = t[0];     bf[p * 2][1] = t[1];
                bf[p * 2 + 1][0] = t[2]; bf[p * 2 + 1][1] = t[3];
            }
            #pragma unroll
            for (int mi = 0; mi < 4; ++mi)
                #pragma unroll
                for (int ni = 0; ni < 8; ++ni)
                    mma_bf16(acc[mi][ni], af[mi], bf[ni]);
        }
    }

    // ---- epilogue: scale by 30, store float2 pairs (even-aligned; N_TOT even)
    const int row_base = m0 + wm * 64 + (lid >> 2);
    const int col_base = n0 + wn * 64 + (lid & 3) * 2;

    #pragma unroll
    for (int mi = 0; mi < 4; ++mi) {
        const int r1 = row_base + mi * 16;
        float* o1 = out + (size_t)r1 * N_TOT;
        float* o2 = out + (size_t)(r1 + 8) * N_TOT;
        #pragma unroll
        for (int ni = 0; ni < 8; ++ni) {
            const int col = col_base + ni * 8;
            if (col < N_TOT) {
                float2 v0, v1;
                v0.x = acc[mi][ni][0] * SCALE;  v0.y = acc[mi][ni][1] * SCALE;
                v1.x = acc[mi][ni][2] * SCALE;  v1.y = acc[mi][ni][3] * SCALE;
                *reinterpret_cast<float2*>(o1 + col) = v0;
                *reinterpret_cast<float2*>(o2 + col) = v1;
            }
        }
    }
}

// ---------------- launch ----------------
extern "C" void kernel_launch(void* const* d_in, const int* in_sizes, int n_in,
                              void* d_out, int out_size)
{
    // metadata order: inputs, non_id_feat, lut, cq, first_pos, second_pos, targets, half, header
    const float* inputs = (const float*)d_in[0];
    const float* nonid  = (const float*)d_in[1];
    const float* lut    = (const float*)d_in[2];
    const float* cq     = (const float*)d_in[3];
    float* out = (float*)d_out;

    pack_kernel<<<(M_TOT + N_PAD) / 4, 256>>>(inputs, lut, cq, nonid);

    cudaFuncSetAttribute(oim_mma_gemm, cudaFuncAttributeMaxDynamicSharedMemorySize, SMEM_BYTES);
    dim3 grid(N_PAD / BN, M_TOT / BM);   // 43 x 16 = 688 CTAs
    oim_mma_gemm<<<grid, NTHREADS, SMEM_BYTES>>>(out);
}

// round 11
// speedup vs baseline: 2.4294x; 2.4294x over previous
#include <cuda_runtime.h>
#include <cuda_fp16.h>
#include <cstdint>

// ---------------- problem constants ----------------
#define M_TOT 2048
#define K_DIM 256
#define N_LUT 5532
#define N_CQ  5000
#define N_TOT 10788
#define N_PAD 11008            // 43 * 256 (zero-padded B rows)
#define SCALE 30.0f

// ---------------- GEMM tiling ----------------
#define BM 128
#define BN 128
#define NCHUNK 4               // 4 chunks of 64 fp16 = K 256 (single fp16 slab)
#define STAGES 3
#define STAGE_BYTES 32768      // A tile 16KB + B tile 16KB (128 rows x 128B)
#define SMEM_BYTES (1024 + STAGES * STAGE_BYTES)
#define NTHREADS 256

typedef unsigned int u32;
typedef unsigned long long u64;

// ---------------- device scratch (no allocs allowed) ----------------
__device__ __align__(1024) __half g_A[(size_t)M_TOT * K_DIM];   // 1 MB
__device__ __align__(1024) __half g_B[(size_t)N_PAD * K_DIM];   // 5.6 MB

// ---------------- PTX helpers (plain sm_80+ features only) ----------------
static __device__ __forceinline__ u32 cvta_smem(const void* p) {
    u32 a;
    asm("{ .reg .u64 t; cvta.to.shared.u64 t, %1; cvt.u32.u64 %0, t; }" : "=r"(a) : "l"(p));
    return a;
}

static __device__ __forceinline__ void cp_async16(u32 dst, const void* src) {
    asm volatile("cp.async.cg.shared.global [%0], [%1], 16;" :: "r"(dst), "l"(src) : "memory");
}

static __device__ __forceinline__ void ldmatrix4(u32* f, u32 addr) {
    asm volatile("ldmatrix.sync.aligned.m8n8.x4.shared.b16 {%0,%1,%2,%3}, [%4];"
                 : "=r"(f[0]), "=r"(f[1]), "=r"(f[2]), "=r"(f[3]) : "r"(addr));
}

static __device__ __forceinline__ void mma_fp16(float* c, const u32* a, const u32* b) {
    asm volatile(
        "mma.sync.aligned.m16n8k16.row.col.f32.f16.f16.f32 "
        "{%0,%1,%2,%3}, {%4,%5,%6,%7}, {%8,%9}, {%0,%1,%2,%3};"
        : "+f"(c[0]), "+f"(c[1]), "+f"(c[2]), "+f"(c[3])
        : "r"(a[0]), "r"(a[1]), "r"(a[2]), "r"(a[3]), "r"(b[0]), "r"(b[1]));
}

// ---------------- pack kernel: fp32 -> fp16 ----------------
__global__ void pack_kernel(const float* __restrict__ A, const float* __restrict__ lut,
                            const float* __restrict__ cq, const float* __restrict__ nonid)
{
    const int t = threadIdx.x;
    const int row = blockIdx.x * 4 + (t >> 6);     // 4 rows per block
    const int k0 = (t & 63) * 4;

    const float* src;
    __half* dst;
    if (row < M_TOT) {
        src = A + (size_t)row * K_DIM;
        dst = g_A + (size_t)row * K_DIM;
    } else {
        const int n = row - M_TOT;
        dst = g_B + (size_t)n * K_DIM;
        if (n < N_LUT)              src = lut   + (size_t)n * K_DIM;
        else if (n < N_LUT + N_CQ)  src = cq    + (size_t)(n - N_LUT) * K_DIM;
        else if (n < N_TOT)         src = nonid + (size_t)(n - N_LUT - N_CQ) * K_DIM;
        else                        src = nullptr;   // zero padding rows
    }

    float4 v = src ? *reinterpret_cast<const float4*>(src + k0)
                   : make_float4(0.f, 0.f, 0.f, 0.f);

    unsigned short h[4];
    h[0] = __half_as_ushort(__float2half_rn(v.x));
    h[1] = __half_as_ushort(__float2half_rn(v.y));
    h[2] = __half_as_ushort(__float2half_rn(v.z));
    h[3] = __half_as_ushort(__float2half_rn(v.w));
    uint2 p;
    p.x = ((u32)h[1] << 16) | h[0];
    p.y = ((u32)h[3] << 16) | h[2];
    *reinterpret_cast<uint2*>(dst + k0) = p;
}

// ---------------- main GEMM: cp.async pipeline + ldmatrix + mma.sync ----------------
__global__ void __launch_bounds__(NTHREADS, 2)
oim_mma_gemm(float* __restrict__ out)
{
    extern __shared__ char smem_raw[];
    u32 base = cvta_smem(smem_raw);
    base = (base + 1023u) & ~1023u;        // 1024-align tile region

    const int tid = threadIdx.x;
    const int lid = tid & 31;
    const int wid = tid >> 5;
    const int wm  = wid & 1;               // 2 warps in M
    const int wn  = wid >> 1;              // 4 warps in N

    const int m0 = blockIdx.y * BM;
    const int n0 = blockIdx.x * BN;

    // ---- producer mapping: each thread copies 4 A + 4 B 16B segments per chunk
    const int r0  = tid >> 3;              // 0..31
    const int seg = tid & 7;               // 16B segment within 128B row

    // ---- ldmatrix lane constants
    const int mat = lid >> 3, rr = lid & 7;
    const int a_row = wm * 64 + ((mat & 1) << 3) + rr;   // + mi*16
    const u32 a_xor = (u32)(a_row & 7);
    const int a_ck  = mat >> 1;                           // 16B chunk within k16
    const int b_row = wn * 32 + ((mat >> 1) << 3) + rr;   // + p*16
    const u32 b_xor = (u32)(b_row & 7);
    const int b_ck  = mat & 1;

    float acc[4][4][4];
    #pragma unroll
    for (int i = 0; i < 4; i++)
        #pragma unroll
        for (int j = 0; j < 4; j++)
            #pragma unroll
            for (int v = 0; v < 4; v++)
                acc[i][j][v] = 0.f;

    // chunk c covers K columns [c*64, c*64+64)
    auto issue_chunk = [&](int c) {
        const int koff = c << 6;
        const u32 stage = base + (u32)(c % STAGES) * STAGE_BYTES;
        const __half* asrc = g_A + (size_t)(m0 + r0) * K_DIM + koff + seg * 8;
        const __half* bsrc = g_B + (size_t)(n0 + r0) * K_DIM + koff + seg * 8;
        #pragma unroll
        for (int j = 0; j < 4; ++j) {
            const u32 rel = (u32)((r0 + j * 32) * 128 + seg * 16);
            const u32 sw  = rel ^ ((rel >> 3) & 0x70u);
            cp_async16(stage + sw,          asrc + (size_t)j * 32 * K_DIM);
            cp_async16(stage + 16384u + sw, bsrc + (size_t)j * 32 * K_DIM);
        }
        asm volatile("cp.async.commit_group;" ::: "memory");
    };

    issue_chunk(0);
    issue_chunk(1);

    for (int q = 0; q < NCHUNK; ++q) {
        if (q < NCHUNK - 2) asm volatile("cp.async.wait_group 1;" ::: "memory");
        else                asm volatile("cp.async.wait_group 0;" ::: "memory");
        __syncthreads();   // chunk q resident; prior reads of recycled stage done

        if (q + 2 < NCHUNK) issue_chunk(q + 2);

        const u32 sA = base + (u32)(q % STAGES) * STAGE_BYTES;
        const u32 sB = sA + 16384u;

        #pragma unroll
        for (int ks = 0; ks < 4; ++ks) {
            u32 af[4][4];
            #pragma unroll
            for (int mi = 0; mi < 4; ++mi) {
                const u32 row  = (u32)(a_row + mi * 16);
                const u32 addr = sA + row * 128u + ((((u32)(ks * 2 + a_ck)) ^ a_xor) << 4);
                ldmatrix4(af[mi], addr);
            }
            u32 bf[4][2];
            #pragma unroll
            for (int p = 0; p < 2; ++p) {
                const u32 row  = (u32)(b_row + p * 16);
                const u32 addr = sB + row * 128u + ((((u32)(ks * 2 + b_ck)) ^ b_xor) << 4);
                u32 t[4];
                ldmatrix4(t, addr);
                bf[p * 2][0] = t[0];     bf[p * 2][1] = t[1];
                bf[p * 2 + 1][0] = t[2]; bf[p * 2 + 1][1] = t[3];
            }
            #pragma unroll
            for (int mi = 0; mi < 4; ++mi)
                #pragma unroll
                for (int ni = 0; ni < 4; ++ni)
                    mma_fp16(acc[mi][ni], af[mi], bf[ni]);
        }
    }

    // ---- epilogue: scale by 30, store float2 pairs (even-aligned; N_TOT even)
    const int row_base = m0 + wm * 64 + (lid >> 2);
    const int col_base = n0 + wn * 32 + (lid & 3) * 2;

    #pragma unroll
    for (int mi = 0; mi < 4; ++mi) {
        const int r1 = row_base + mi * 16;
        float* o1 = out + (size_t)r1 * N_TOT;
        float* o2 = out + (size_t)(r1 + 8) * N_TOT;
        #pragma unroll
        for (int ni = 0; ni < 4; ++ni) {
            const int col = col_base + ni * 8;
            if (col < N_TOT) {
                float2 v0, v1;
                v0.x = acc[mi][ni][0] * SCALE;  v0.y = acc[mi][ni][1] * SCALE;
                v1.x = acc[mi][ni][2] * SCALE;  v1.y = acc[mi][ni][3] * SCALE;
                *reinterpret_cast<float2*>(o1 + col) = v0;
                *reinterpret_cast<float2*>(o2 + col) = v1;
            }
        }
    }
}

// ---------------- launch ----------------
extern "C" void kernel_launch(void* const* d_in, const int* in_sizes, int n_in,
                              void* d_out, int out_size)
{
    // metadata order: inputs, non_id_feat, lut, cq, first_pos, second_pos, targets, half, header
    const float* inputs = (const float*)d_in[0];
    const float* nonid  = (const float*)d_in[1];
    const float* lut    = (const float*)d_in[2];
    const float* cq     = (const float*)d_in[3];
    float* out = (float*)d_out;

    pack_kernel<<<(M_TOT + N_PAD) / 4, 256>>>(inputs, lut, cq, nonid);

    cudaFuncSetAttribute(oim_mma_gemm, cudaFuncAttributeMaxDynamicSharedMemorySize, SMEM_BYTES);
    dim3 grid((N_TOT + BN - 1) / BN, M_TOT / BM);   // 85 x 16
    oim_mma_gemm<<<grid, NTHREADS, SMEM_BYTES>>>(out);
}